// round 10
// baseline (speedup 1.0000x reference)
#include <cuda_runtime.h>
#include <cstdint>

#define TT 512
#define BB 1024
#define CC 64
#define FULLMASK 0xFFFFFFFFu
#define WPB 4
#define GRID2 128

typedef unsigned long long u64;

__device__ float g_part[BB];
__device__ int   g_lpart[8][BB];
__device__ int   g_len[BB];
__device__ int   g_order[BB];      // chain ids, descending length

// ---- packed f32x2 helpers ----
static __device__ __forceinline__ u64 fma2(u64 a, u64 b, u64 c) {
    u64 r;
    asm("fma.rn.f32x2 %0, %1, %2, %3;" : "=l"(r) : "l"(a), "l"(b), "l"(c));
    return r;
}
static __device__ __forceinline__ u64 add2(u64 a, u64 b) {
    u64 r;
    asm("add.rn.f32x2 %0, %1, %2;" : "=l"(r) : "l"(a), "l"(b));
    return r;
}
static __device__ __forceinline__ u64 pack2(float lo, float hi) {
    u64 r;
    asm("mov.b64 %0, {%1, %2};" : "=l"(r) : "f"(lo), "f"(hi));
    return r;
}
static __device__ __forceinline__ float hadd2(u64 a) {
    float lo, hi;
    asm("mov.b64 {%0, %1}, %2;" : "=f"(lo), "=f"(hi) : "l"(a));
    return lo + hi;
}

// ---- pre-pass 1: per-slice partial lengths (coalesced) ----
__global__ void crf_len(const float* __restrict__ mask) {
    const int b = threadIdx.x;
    const int k = blockIdx.x;
    float c = 0.0f;
#pragma unroll 8
    for (int t = k * 64; t < (k + 1) * 64; t++)
        c += mask[t * BB + b];
    g_lpart[k][b] = (int)c;
}

// ---- pre-pass 2: counting sort by length, descending ----
__global__ void crf_sort() {
    __shared__ int hist[TT + 1];
    __shared__ int off[TT + 1];
    const int b = threadIdx.x;
    if (b <= TT) hist[b] = 0;
    __syncthreads();
    int len = 0;
#pragma unroll
    for (int k = 0; k < 8; k++) len += g_lpart[k][b];
    g_len[b] = len;
    atomicAdd(&hist[len], 1);
    __syncthreads();
    if (b == 0) {
        int acc = 0;
        for (int l = TT; l >= 0; l--) { off[l] = acc; acc += hist[l]; }
    }
    __syncthreads();
    const int r = atomicAdd(&off[len], 1);
    g_order[r] = b;
}

// One recursion step for chain `ci` of this warp (macro: keeps rings/accs in regs).
// ring[s] must be h(tcur); refills slot s with h(tcur+4).
#define STEPC(ring, s, tcur, hoff, ci, buf, p0, p1, nrm, Cc, do_norm)           \
    do {                                                                        \
        const float2 hc = ring[s];                                              \
        float rr = 1.0f;                                                        \
        if (do_norm) {                                                          \
            const float nv = __shfl_sync(FULLMASK, nrm, 1);                     \
            rr = __fdividef(1.0f, nv);                                          \
            Cc += __logf(nv);                                                   \
        }                                                                       \
        const float eh0 = __expf(hc.x);                                         \
        const float eh1 = __expf(hc.y);                                         \
        const ulonglong2* pv = (const ulonglong2*)p_sh[wid][ci][buf];           \
        u64 a0[4] = {0, 0, 0, 0};                                               \
        u64 a1[4] = {0, 0, 0, 0};                                               \
        _Pragma("unroll")                                                       \
        for (int k = 0; k < 16; k++) {                                          \
            ulonglong2 q = pv[k];                                               \
            const int c = 2 * (k & 1);                                          \
            a0[c]     = fma2(e0[2 * k],     q.x, a0[c]);                        \
            a0[c + 1] = fma2(e0[2 * k + 1], q.y, a0[c + 1]);                    \
            a1[c]     = fma2(e1[2 * k],     q.x, a1[c]);                        \
            a1[c + 1] = fma2(e1[2 * k + 1], q.y, a1[c + 1]);                    \
        }                                                                       \
        const float acc0 = hadd2(add2(add2(a0[0], a0[1]), add2(a0[2], a0[3]))); \
        const float acc1 = hadd2(add2(add2(a1[0], a1[1]), add2(a1[2], a1[3]))); \
        if (do_norm) { p0 = acc0 * rr * eh0; p1 = acc1 * rr * eh1; }            \
        else         { p0 = acc0 * eh0;      p1 = acc1 * eh1;      }            \
        nrm = p1;                                                               \
        p_sh[wid][ci][buf ^ 1][lane] = pack2(p0, p1);                           \
        buf ^= 1;                                                               \
        int tf = (tcur) + 4;                                                    \
        if (tf > TT - 1) tf = TT - 1;                                           \
        ring[s] = hp[(size_t)tf * HROW + hoff];                                 \
    } while (0)

// Two chains per warp (ranks W and 1023-W: lenA+lenB ~ const -> self-balanced).
// 128 independent FFMA2 per step-pair keep the SMSP fma pipe fed from one warp.
__global__ void __launch_bounds__(WPB * 32, 1) crf_chain(
    const float* __restrict__ h,      // (T, B, C)
    const int*   __restrict__ y0,     // (T+1, B)
    const float* __restrict__ mask,   // unused
    const float* __restrict__ trans)  // (C, C)
{
    __shared__ __align__(16) float tr_sh[CC * CC];
    __shared__ __align__(16) float E_sh[CC * CC];
    __shared__ __align__(16) u64   p_sh[WPB][2][2][32];  // [warp][chain][buf][lane]

    const int tid  = threadIdx.x;
    const int lane = tid & 31;
    const int wid  = tid >> 5;

    {
        const float4* g4 = (const float4*)trans;
        float4*       t4 = (float4*)tr_sh;
        float4*       e4 = (float4*)E_sh;
#pragma unroll
        for (int k = 0; k < (CC * CC / 4) / (WPB * 32); k++) {
            const int    idx = tid + WPB * 32 * k;
            const float4 v   = g4[idx];
            t4[idx] = v;
            float4 e;
            e.x = __expf(v.x); e.y = __expf(v.y);
            e.z = __expf(v.z); e.w = __expf(v.w);
            e4[idx] = e;
        }
    }
    __syncthreads();

    const int W    = blockIdx.x * WPB + wid;        // 0..511
    const int bA   = g_order[W];                    // longer chain
    const int bB   = g_order[BB - 1 - W];           // shorter chain
    const int lenA = g_len[bA];
    const int lenB = g_len[bB];
    const int j0   = 2 * lane;
    const int j1   = 2 * lane + 1;

    // E rows -> registers (shared by both chains)
    u64 e0[32], e1[32];
    {
        const ulonglong2* ge = (const ulonglong2*)E_sh;
#pragma unroll
        for (int k = 0; k < 16; k++) {
            ulonglong2 q0 = ge[j0 * 16 + k];
            ulonglong2 q1 = ge[j1 * 16 + k];
            e0[2 * k] = q0.x; e0[2 * k + 1] = q0.y;
            e1[2 * k] = q1.x; e1[2 * k + 1] = q1.y;
        }
    }

    // init both chains: v one-hot at SOS(=1)
    float pA0 = (j0 == 1) ? 1.0f : 0.0f;
    float pA1 = (j1 == 1) ? 1.0f : 0.0f;
    float pB0 = pA0, pB1 = pA1;
    float nrmA = 1.0f, nrmB = 1.0f;
    float CcA = 0.0f, CcB = 0.0f;
    p_sh[wid][0][0][lane] = pack2(pA0, pA1);
    p_sh[wid][1][0][lane] = pack2(pB0, pB1);
    __syncwarp();

    const float2* hp    = (const float2*)h;
    const int     HROW  = BB * CC / 2;
    const int     hoffA = bA * (CC / 2) + lane;
    const int     hoffB = bB * (CC / 2) + lane;
    float2 rA[4], rB[4];
#pragma unroll
    for (int k = 0; k < 4; k++) {
        rA[k] = hp[(size_t)k * HROW + hoffA];
        rB[k] = hp[(size_t)k * HROW + hoffB];
    }
    int bufA = 0, bufB = 0;

    // ---- lockstep phase: both chains, t in [0, lenB) ----
    const int lock4 = lenB & ~3;
    int t = 0;
#pragma unroll 1
    for (; t < lock4; t += 4) {
#pragma unroll
        for (int s = 0; s < 4; s++) {
            STEPC(rA, s, t + s, hoffA, 0, bufA, pA0, pA1, nrmA, CcA, s == 0);
            STEPC(rB, s, t + s, hoffB, 1, bufB, pB0, pB1, nrmB, CcB, s == 0);
            __syncwarp();
        }
    }
#pragma unroll
    for (int s = 0; s < 4; s++) {
        if (t + s >= lenB) break;
        STEPC(rA, s, t + s, hoffA, 0, bufA, pA0, pA1, nrmA, CcA, s == 0);
        STEPC(rB, s, t + s, hoffB, 1, bufB, pB0, pB1, nrmB, CcB, s == 0);
        __syncwarp();
    }

    // ---- solo phase: chain A, t in [lenB, lenA) ----
#pragma unroll
    for (int k = 0; k < 4; k++) {        // re-seed A ring at t = lenB+k
        int tf = lenB + k;
        if (tf > TT - 1) tf = TT - 1;
        rA[k] = hp[(size_t)tf * HROW + hoffA];
    }
    const int rem  = lenA - lenB;
    const int rem4 = rem & ~3;
    int u = 0;
#pragma unroll 1
    for (; u < rem4; u += 4) {
#pragma unroll
        for (int s = 0; s < 4; s++) {
            STEPC(rA, s, lenB + u + s, hoffA, 0, bufA, pA0, pA1, nrmA, CcA, s == 0);
            __syncwarp();
        }
    }
#pragma unroll
    for (int s = 0; s < 4; s++) {
        if (u + s >= rem) break;
        STEPC(rA, s, lenB + u + s, hoffA, 0, bufA, pA0, pA1, nrmA, CcA, s == 0);
        __syncwarp();
    }

    // ---- finalize both chains ----
#pragma unroll
    for (int ci = 0; ci < 2; ci++) {
        const float p0  = ci ? pB0 : pA0;
        const float p1  = ci ? pB1 : pA1;
        const float Cc  = ci ? CcB : CcA;
        const int   b   = ci ? bB : bA;
        const int   len = ci ? lenB : lenA;

        float v = p0 * E_sh[2 * CC + j0] + p1 * E_sh[2 * CC + j1];
#pragma unroll
        for (int o = 16; o; o >>= 1) v += __shfl_xor_sync(FULLMASK, v, o);
        const float zf = Cc + __logf(v);

        float S = 0.0f;
        const int tmax = (len < TT - 1) ? len : (TT - 1);
#pragma unroll
        for (int k = 0; k < 16; k++) {
            const int tt = lane + 32 * k;
            if (tt < tmax) {
                const int ya = y0[tt * BB + b];
                const int yb = y0[(tt + 1) * BB + b];
                const float hv = h[(size_t)tt * (BB * CC) + b * CC + yb];
                S += hv + tr_sh[yb * CC + ya];
            }
        }
#pragma unroll
        for (int o = 16; o; o >>= 1) S += __shfl_xor_sync(FULLMASK, S, o);

        if (lane == 0) {
            const int last = y0[len * BB + b];
            g_part[b] = zf - (S + tr_sh[0 * CC + last]);
        }
    }
}

// Deterministic tree reduction of the 1024 per-chain results.
__global__ void crf_reduce(float* __restrict__ out) {
    __shared__ float sh[256];
    const int t = threadIdx.x;
    float s = 0.0f;
#pragma unroll
    for (int k = 0; k < 4; k++) s += g_part[t + 256 * k];
    sh[t] = s;
    __syncthreads();
    for (int o = 128; o; o >>= 1) {
        if (t < o) sh[t] += sh[t + o];
        __syncthreads();
    }
    if (t == 0) out[0] = sh[0] * (1.0f / 1024.0f);
}

extern "C" void kernel_launch(void* const* d_in, const int* in_sizes, int n_in,
                              void* d_out, int out_size) {
    const float* h     = nullptr;
    const int*   y0    = nullptr;
    const float* mask  = nullptr;
    const float* trans = nullptr;
    for (int i = 0; i < n_in; i++) {
        const long n = (long)in_sizes[i];
        if      (n == (long)TT * BB * CC)  h     = (const float*)d_in[i];
        else if (n == (long)(TT + 1) * BB) y0    = (const int*)d_in[i];
        else if (n == (long)TT * BB)       mask  = (const float*)d_in[i];
        else if (n == (long)CC * CC)       trans = (const float*)d_in[i];
    }

    crf_len<<<8, BB>>>(mask);
    crf_sort<<<1, BB>>>();
    crf_chain<<<GRID2, WPB * 32>>>(h, y0, mask, trans);
    crf_reduce<<<1, 256>>>((float*)d_out);
}

// round 11
// speedup vs baseline: 1.0491x; 1.0491x over previous
#include <cuda_runtime.h>
#include <cstdint>

#define TT 512
#define BB 1024
#define CC 64
#define FULLMASK 0xFFFFFFFFu
#define WPB 4
#define GRIDC 148
#define NSINGLE 160   // 1024 = 160 singles + 432 pairs

typedef unsigned long long u64;

__device__ float g_part[BB];
__device__ int   g_lpart[8][BB];
__device__ int   g_len[BB];
__device__ int   g_order[BB];      // chain ids, descending length

// ---- packed f32x2 helpers ----
static __device__ __forceinline__ u64 fma2(u64 a, u64 b, u64 c) {
    u64 r;
    asm("fma.rn.f32x2 %0, %1, %2, %3;" : "=l"(r) : "l"(a), "l"(b), "l"(c));
    return r;
}
static __device__ __forceinline__ u64 add2(u64 a, u64 b) {
    u64 r;
    asm("add.rn.f32x2 %0, %1, %2;" : "=l"(r) : "l"(a), "l"(b));
    return r;
}
static __device__ __forceinline__ u64 pack2(float lo, float hi) {
    u64 r;
    asm("mov.b64 %0, {%1, %2};" : "=l"(r) : "f"(lo), "f"(hi));
    return r;
}
static __device__ __forceinline__ float hadd2(u64 a) {
    float lo, hi;
    asm("mov.b64 {%0, %1}, %2;" : "=f"(lo), "=f"(hi) : "l"(a));
    return lo + hi;
}

// ---- pre-pass 1: per-slice partial lengths (coalesced) ----
__global__ void crf_len(const float* __restrict__ mask) {
    const int b = threadIdx.x;
    const int k = blockIdx.x;
    float c = 0.0f;
#pragma unroll 8
    for (int t = k * 64; t < (k + 1) * 64; t++)
        c += mask[t * BB + b];
    g_lpart[k][b] = (int)c;
}

// ---- pre-pass 2: counting sort by length, descending ----
__global__ void crf_sort() {
    __shared__ int hist[TT + 1];
    __shared__ int off[TT + 1];
    const int b = threadIdx.x;
    if (b <= TT) hist[b] = 0;
    __syncthreads();
    int len = 0;
#pragma unroll
    for (int k = 0; k < 8; k++) len += g_lpart[k][b];
    g_len[b] = len;
    atomicAdd(&hist[len], 1);
    __syncthreads();
    if (b == 0) {
        int acc = 0;
        for (int l = TT; l >= 0; l--) { off[l] = acc; acc += hist[l]; }
    }
    __syncthreads();
    const int r = atomicAdd(&off[len], 1);
    g_order[r] = b;
}

// One recursion step for chain `ci` of this warp. ring[s] holds h(tcur);
// refills slot s with h(tcur+4).
#define STEPC(ring, s, tcur, hoff, ci, buf, p0, p1, nrm, Cc, do_norm)           \
    do {                                                                        \
        const float2 hc = ring[s];                                              \
        float rr = 1.0f;                                                        \
        if (do_norm) {                                                          \
            const float nv = __shfl_sync(FULLMASK, nrm, 1);                     \
            rr = __fdividef(1.0f, nv);                                          \
            Cc += __logf(nv);                                                   \
        }                                                                       \
        const float eh0 = __expf(hc.x);                                         \
        const float eh1 = __expf(hc.y);                                         \
        const ulonglong2* pv = (const ulonglong2*)p_sh[wid][ci][buf];           \
        u64 a0[4] = {0, 0, 0, 0};                                               \
        u64 a1[4] = {0, 0, 0, 0};                                               \
        _Pragma("unroll")                                                       \
        for (int k = 0; k < 16; k++) {                                          \
            ulonglong2 q = pv[k];                                               \
            const int c = 2 * (k & 1);                                          \
            a0[c]     = fma2(e0[2 * k],     q.x, a0[c]);                        \
            a0[c + 1] = fma2(e0[2 * k + 1], q.y, a0[c + 1]);                    \
            a1[c]     = fma2(e1[2 * k],     q.x, a1[c]);                        \
            a1[c + 1] = fma2(e1[2 * k + 1], q.y, a1[c + 1]);                    \
        }                                                                       \
        const float acc0 = hadd2(add2(add2(a0[0], a0[1]), add2(a0[2], a0[3]))); \
        const float acc1 = hadd2(add2(add2(a1[0], a1[1]), add2(a1[2], a1[3]))); \
        if (do_norm) { p0 = acc0 * rr * eh0; p1 = acc1 * rr * eh1; }            \
        else         { p0 = acc0 * eh0;      p1 = acc1 * eh1;      }            \
        nrm = p1;                                                               \
        p_sh[wid][ci][buf ^ 1][lane] = pack2(p0, p1);                           \
        buf ^= 1;                                                               \
        int tf = (tcur) + 4;                                                    \
        if (tf > TT - 1) tf = TT - 1;                                           \
        ring[s] = hp[(size_t)tf * HROW + hoff];                                 \
    } while (0)

// 148 blocks x 4 warps = 592 warps (1 per SMSP chip-wide).
// Warps 0..159: single chain (the 160 longest). Warps 160..591: two chains
// paired long+short (rank 160+i with 1023-i, sum ~const) -> issue-bound
// lockstep with latency self-hiding, minimal solo tail.
__global__ void __launch_bounds__(WPB * 32, 1) crf_chain(
    const float* __restrict__ h,      // (T, B, C)
    const int*   __restrict__ y0,     // (T+1, B)
    const float* __restrict__ mask,   // unused
    const float* __restrict__ trans)  // (C, C)
{
    __shared__ __align__(16) float tr_sh[CC * CC];
    __shared__ __align__(16) float E_sh[CC * CC];
    __shared__ __align__(16) u64   p_sh[WPB][2][2][32];  // [warp][chain][buf][lane]

    const int tid  = threadIdx.x;
    const int lane = tid & 31;
    const int wid  = tid >> 5;

    {
        const float4* g4 = (const float4*)trans;
        float4*       t4 = (float4*)tr_sh;
        float4*       e4 = (float4*)E_sh;
#pragma unroll
        for (int k = 0; k < (CC * CC / 4) / (WPB * 32); k++) {
            const int    idx = tid + WPB * 32 * k;
            const float4 v   = g4[idx];
            t4[idx] = v;
            float4 e;
            e.x = __expf(v.x); e.y = __expf(v.y);
            e.z = __expf(v.z); e.w = __expf(v.w);
            e4[idx] = e;
        }
    }
    __syncthreads();

    const int W = blockIdx.x * WPB + wid;   // 0..591
    const bool dual = (W >= NSINGLE);
    const int  i    = W - NSINGLE;
    const int  bA   = dual ? g_order[NSINGLE + i] : g_order[W];
    const int  bB   = dual ? g_order[BB - 1 - i]  : bA;
    const int  lenA = g_len[bA];
    const int  lenB = dual ? g_len[bB] : 0;   // singles: no lockstep phase
    const int  j0   = 2 * lane;
    const int  j1   = 2 * lane + 1;

    // E rows -> registers (shared by both chains)
    u64 e0[32], e1[32];
    {
        const ulonglong2* ge = (const ulonglong2*)E_sh;
#pragma unroll
        for (int k = 0; k < 16; k++) {
            ulonglong2 q0 = ge[j0 * 16 + k];
            ulonglong2 q1 = ge[j1 * 16 + k];
            e0[2 * k] = q0.x; e0[2 * k + 1] = q0.y;
            e1[2 * k] = q1.x; e1[2 * k + 1] = q1.y;
        }
    }

    // init: v one-hot at SOS(=1)
    float pA0 = (j0 == 1) ? 1.0f : 0.0f;
    float pA1 = (j1 == 1) ? 1.0f : 0.0f;
    float pB0 = pA0, pB1 = pA1;
    float nrmA = 1.0f, nrmB = 1.0f;
    float CcA = 0.0f, CcB = 0.0f;
    p_sh[wid][0][0][lane] = pack2(pA0, pA1);
    p_sh[wid][1][0][lane] = pack2(pB0, pB1);
    __syncwarp();

    const float2* hp    = (const float2*)h;
    const int     HROW  = BB * CC / 2;
    const int     hoffA = bA * (CC / 2) + lane;
    const int     hoffB = bB * (CC / 2) + lane;
    float2 rA[4], rB[4];
#pragma unroll
    for (int k = 0; k < 4; k++) {
        rA[k] = hp[(size_t)k * HROW + hoffA];
        rB[k] = hp[(size_t)k * HROW + hoffB];
    }
    int bufA = 0, bufB = 0;

    // ---- lockstep phase (dual warps only): t in [0, lenB) ----
    const int lock4 = lenB & ~3;
    int t = 0;
#pragma unroll 1
    for (; t < lock4; t += 4) {
#pragma unroll
        for (int s = 0; s < 4; s++) {
            STEPC(rA, s, t + s, hoffA, 0, bufA, pA0, pA1, nrmA, CcA, s == 0);
            STEPC(rB, s, t + s, hoffB, 1, bufB, pB0, pB1, nrmB, CcB, s == 0);
            __syncwarp();
        }
    }
#pragma unroll
    for (int s = 0; s < 4; s++) {
        if (t + s >= lenB) break;
        STEPC(rA, s, t + s, hoffA, 0, bufA, pA0, pA1, nrmA, CcA, s == 0);
        STEPC(rB, s, t + s, hoffB, 1, bufB, pB0, pB1, nrmB, CcB, s == 0);
        __syncwarp();
    }

    // ---- solo phase: chain A, t in [lenB, lenA)  (singles: lenB=0 -> all here) ----
#pragma unroll
    for (int k = 0; k < 4; k++) {        // re-seed A ring at t = lenB+k
        int tf = lenB + k;
        if (tf > TT - 1) tf = TT - 1;
        rA[k] = hp[(size_t)tf * HROW + hoffA];
    }
    const int rem  = lenA - lenB;
    const int rem4 = rem & ~3;
    int u = 0;
#pragma unroll 1
    for (; u < rem4; u += 4) {
#pragma unroll
        for (int s = 0; s < 4; s++) {
            STEPC(rA, s, lenB + u + s, hoffA, 0, bufA, pA0, pA1, nrmA, CcA, s == 0);
            __syncwarp();
        }
    }
#pragma unroll
    for (int s = 0; s < 4; s++) {
        if (u + s >= rem) break;
        STEPC(rA, s, lenB + u + s, hoffA, 0, bufA, pA0, pA1, nrmA, CcA, s == 0);
        __syncwarp();
    }

    // ---- finalize (chain A always; chain B only for dual warps) ----
    const int nchain = dual ? 2 : 1;
#pragma unroll
    for (int ci = 0; ci < 2; ci++) {
        if (ci >= nchain) break;
        const float p0  = ci ? pB0 : pA0;
        const float p1  = ci ? pB1 : pA1;
        const float Cc  = ci ? CcB : CcA;
        const int   b   = ci ? bB : bA;
        const int   len = ci ? lenB : lenA;

        float v = p0 * E_sh[2 * CC + j0] + p1 * E_sh[2 * CC + j1];
#pragma unroll
        for (int o = 16; o; o >>= 1) v += __shfl_xor_sync(FULLMASK, v, o);
        const float zf = Cc + __logf(v);

        float S = 0.0f;
        const int tmax = (len < TT - 1) ? len : (TT - 1);
#pragma unroll
        for (int k = 0; k < 16; k++) {
            const int tt = lane + 32 * k;
            if (tt < tmax) {
                const int ya = y0[tt * BB + b];
                const int yb = y0[(tt + 1) * BB + b];
                const float hv = h[(size_t)tt * (BB * CC) + b * CC + yb];
                S += hv + tr_sh[yb * CC + ya];
            }
        }
#pragma unroll
        for (int o = 16; o; o >>= 1) S += __shfl_xor_sync(FULLMASK, S, o);

        if (lane == 0) {
            const int last = y0[len * BB + b];
            g_part[b] = zf - (S + tr_sh[0 * CC + last]);
        }
    }
}

// Deterministic tree reduction of the 1024 per-chain results.
__global__ void crf_reduce(float* __restrict__ out) {
    __shared__ float sh[256];
    const int t = threadIdx.x;
    float s = 0.0f;
#pragma unroll
    for (int k = 0; k < 4; k++) s += g_part[t + 256 * k];
    sh[t] = s;
    __syncthreads();
    for (int o = 128; o; o >>= 1) {
        if (t < o) sh[t] += sh[t + o];
        __syncthreads();
    }
    if (t == 0) out[0] = sh[0] * (1.0f / 1024.0f);
}

extern "C" void kernel_launch(void* const* d_in, const int* in_sizes, int n_in,
                              void* d_out, int out_size) {
    const float* h     = nullptr;
    const int*   y0    = nullptr;
    const float* mask  = nullptr;
    const float* trans = nullptr;
    for (int i = 0; i < n_in; i++) {
        const long n = (long)in_sizes[i];
        if      (n == (long)TT * BB * CC)  h     = (const float*)d_in[i];
        else if (n == (long)(TT + 1) * BB) y0    = (const int*)d_in[i];
        else if (n == (long)TT * BB)       mask  = (const float*)d_in[i];
        else if (n == (long)CC * CC)       trans = (const float*)d_in[i];
    }

    crf_len<<<8, BB>>>(mask);
    crf_sort<<<1, BB>>>();
    crf_chain<<<GRIDC, WPB * 32>>>(h, y0, mask, trans);
    crf_reduce<<<1, 256>>>((float*)d_out);
}

// round 14
// speedup vs baseline: 1.1659x; 1.1113x over previous
#include <cuda_runtime.h>
#include <cstdint>

#define TT 512
#define BB 1024
#define CC 64
#define FULLMASK 0xFFFFFFFFu
#define GRIDC 148
#define NWARP 8
#define NPAIRB 108   // blocks 0..107 paired (ranks 0..863), 108..147 solo (864..1023)

typedef unsigned long long u64;

__device__ float g_part[BB];
__device__ int   g_lpart[8][BB];
__device__ int   g_len[BB];
__device__ int   g_order[BB];      // chain ids, descending length

// ---- packed f32x2 helpers ----
static __device__ __forceinline__ u64 fma2(u64 a, u64 b, u64 c) {
    u64 r;
    asm("fma.rn.f32x2 %0, %1, %2, %3;" : "=l"(r) : "l"(a), "l"(b), "l"(c));
    return r;
}
static __device__ __forceinline__ u64 add2(u64 a, u64 b) {
    u64 r;
    asm("add.rn.f32x2 %0, %1, %2;" : "=l"(r) : "l"(a), "l"(b));
    return r;
}
static __device__ __forceinline__ u64 pack2(float lo, float hi) {
    u64 r;
    asm("mov.b64 %0, {%1, %2};" : "=l"(r) : "f"(lo), "f"(hi));
    return r;
}
static __device__ __forceinline__ float hadd2(u64 a) {
    float lo, hi;
    asm("mov.b64 {%0, %1}, %2;" : "=f"(lo), "=f"(hi) : "l"(a));
    return lo + hi;
}

// ---- pre-pass 1: per-slice partial lengths (coalesced) ----
__global__ void crf_len(const float* __restrict__ mask) {
    const int b = threadIdx.x;
    const int k = blockIdx.x;
    float c = 0.0f;
#pragma unroll 8
    for (int t = k * 64; t < (k + 1) * 64; t++)
        c += mask[t * BB + b];
    g_lpart[k][b] = (int)c;
}

// ---- pre-pass 2: counting sort by length, descending ----
__global__ void crf_sort() {
    __shared__ int hist[TT + 1];
    __shared__ int off[TT + 1];
    const int b = threadIdx.x;
    if (b <= TT) hist[b] = 0;
    __syncthreads();
    int len = 0;
#pragma unroll
    for (int k = 0; k < 8; k++) len += g_lpart[k][b];
    g_len[b] = len;
    atomicAdd(&hist[len], 1);
    __syncthreads();
    if (b == 0) {
        int acc = 0;
        for (int l = TT; l >= 0; l--) { off[l] = acc; acc += hist[l]; }
    }
    __syncthreads();
    const int r = atomicAdd(&off[len], 1);
    g_order[r] = b;
}

// pad launch so ncu's "-s 5 -c 1" lands on crf_chain (6th launch)
__global__ void crf_nop() {}

// One warp per chain. Paired blocks (bl<108): SMSP g=4*bl+s runs sorted ranks
// g (wid<4) and 863-g (wid>=4) — pair step-sums ~const => equal fma-pipe time.
// Solo blocks (bl>=108): wid<4 run the 160 shortest chains alone; wid>=4 idle.
__global__ void __launch_bounds__(NWARP * 32) crf_chain(
    const float* __restrict__ h,      // (T, B, C)
    const int*   __restrict__ y0,     // (T+1, B)
    const float* __restrict__ mask,   // unused
    const float* __restrict__ trans)  // (C, C)
{
    __shared__ __align__(16) float tr_sh[CC * CC];
    __shared__ __align__(16) float E_sh[CC * CC];          // exp(trans)
    __shared__ __align__(16) u64   p_sh[NWARP][2][32];

    const int tid  = threadIdx.x;
    const int lane = tid & 31;
    const int wid  = tid >> 5;

    // cooperative fill: trans -> tr_sh, exp(trans) -> E_sh
    {
        const float4* g4 = (const float4*)trans;
        float4*       t4 = (float4*)tr_sh;
        float4*       e4 = (float4*)E_sh;
#pragma unroll
        for (int k = 0; k < (CC * CC / 4) / (NWARP * 32); k++) {
            const int    idx = tid + NWARP * 32 * k;
            const float4 v   = g4[idx];
            t4[idx] = v;
            float4 e;
            e.x = __expf(v.x); e.y = __expf(v.y);
            e.z = __expf(v.z); e.w = __expf(v.w);
            e4[idx] = e;
        }
    }
    __syncthreads();

    // rank mapping (fma-time balanced)
    const int bl = blockIdx.x;
    int rank;
    if (bl < NPAIRB) {
        const int g = 4 * bl + (wid & 3);          // SMSP id 0..431
        rank = (wid < 4) ? g : (863 - g);
    } else {
        if (wid >= 4) return;                      // solo blocks: 4 warps only
        rank = 864 + 4 * (bl - NPAIRB) + wid;      // 864..1023
    }
    const int b   = g_order[rank];
    const int len = g_len[b];
    const int j0  = 2 * lane;
    const int j1  = 2 * lane + 1;

    // E rows -> registers as packed f32x2 pairs
    u64 e0[32], e1[32];
    {
        const ulonglong2* ge = (const ulonglong2*)E_sh;
#pragma unroll
        for (int k = 0; k < 16; k++) {
            ulonglong2 q0 = ge[j0 * 16 + k];
            ulonglong2 q1 = ge[j1 * 16 + k];
            e0[2 * k] = q0.x; e0[2 * k + 1] = q0.y;
            e1[2 * k] = q1.x; e1[2 * k + 1] = q1.y;
        }
    }

    // init: v one-hot at SOS(=1); Ccum = 0; normalizer seeded to 1
    float pc0 = (j0 == 1) ? 1.0f : 0.0f;
    float pc1 = (j1 == 1) ? 1.0f : 0.0f;
    float nrm_reg = 1.0f;     // lane 1's copy tracks v[3]
    float Ccum = 0.0f;
    p_sh[wid][0][lane] = pack2(pc0, pc1);
    __syncwarp();

    // 8-deep indexed h ring (float2/lane/step), slot = t & 7
    const float2* hp   = (const float2*)h;
    const int     HROW = BB * CC / 2;
    const int     hoff = b * (CC / 2) + lane;
    float2 hb[8];
#pragma unroll
    for (int k = 0; k < 8; k++) hb[k] = hp[(size_t)k * HROW + hoff];

    int buf = 0;

    // one step; s = static ring slot; norm every 4 steps (range-safe: growth
    // <= e^32 between norms, spread <= e^15, inside fp32)
    auto step = [&](int tcur, int s, bool do_norm) __attribute__((always_inline)) {
        const float2 hc  = hb[s];
        float r = 1.0f;
        if (do_norm) {
            const float nrm = __shfl_sync(FULLMASK, nrm_reg, 1);
            r = __fdividef(1.0f, nrm);
            Ccum += __logf(nrm);
        }
        const float eh0 = __expf(hc.x);
        const float eh1 = __expf(hc.y);

        const ulonglong2* pv = (const ulonglong2*)p_sh[wid][buf];
        u64 a0[4] = {0, 0, 0, 0};
        u64 a1[4] = {0, 0, 0, 0};
#pragma unroll
        for (int k = 0; k < 16; k++) {
            ulonglong2 q = pv[k];
            const int  c = 2 * (k & 1);
            a0[c]     = fma2(e0[2 * k],     q.x, a0[c]);
            a0[c + 1] = fma2(e0[2 * k + 1], q.y, a0[c + 1]);
            a1[c]     = fma2(e1[2 * k],     q.x, a1[c]);
            a1[c + 1] = fma2(e1[2 * k + 1], q.y, a1[c + 1]);
        }
        const float acc0 = hadd2(add2(add2(a0[0], a0[1]), add2(a0[2], a0[3])));
        const float acc1 = hadd2(add2(add2(a1[0], a1[1]), add2(a1[2], a1[3])));

        if (do_norm) { pc0 = acc0 * r * eh0; pc1 = acc1 * r * eh1; }
        else         { pc0 = acc0 * eh0;     pc1 = acc1 * eh1;     }
        nrm_reg = pc1;                        // lane 1's pc1 == v[3]
        p_sh[wid][buf ^ 1][lane] = pack2(pc0, pc1);
        buf ^= 1;

        int tf = tcur + 8;
        if (tf > TT - 1) tf = TT - 1;
        hb[s] = hp[(size_t)tf * HROW + hoff];
        __syncwarp();
    };

    // counted main loop, then break-able tail chunk (warp-private control flow)
    const int len8 = len & ~7;
    int t = 0;
#pragma unroll 1
    for (; t < len8; t += 8) {
#pragma unroll
        for (int s = 0; s < 8; s++) step(t + s, s, (s & 3) == 0);
    }
#pragma unroll
    for (int s = 0; s < 8; s++) {
        if (t + s >= len) break;
        step(t + s, s, (s & 3) == 0);
    }

    // final: Zf = Ccum + log( sum_j v_j * exp(trans[EOS, j]) )
    float v = pc0 * E_sh[2 * CC + j0] + pc1 * E_sh[2 * CC + j1];
#pragma unroll
    for (int o = 16; o; o >>= 1) v += __shfl_xor_sync(FULLMASK, v, o);
    const float zf = Ccum + __logf(v);

    // score: S = sum_{t<min(len,T-1)} h[t,b,y0[t+1]] + trans[y0[t+1],y0[t]]
    float S = 0.0f;
    {
        const int tmax = (len < TT - 1) ? len : (TT - 1);
#pragma unroll
        for (int k = 0; k < 16; k++) {
            const int tt = lane + 32 * k;
            if (tt < tmax) {
                const int ya = y0[tt * BB + b];
                const int yb = y0[(tt + 1) * BB + b];
                const float hv = h[(size_t)tt * (BB * CC) + b * CC + yb];
                S += hv + tr_sh[yb * CC + ya];
            }
        }
#pragma unroll
        for (int o = 16; o; o >>= 1) S += __shfl_xor_sync(FULLMASK, S, o);
    }

    if (lane == 0) {
        const int last = y0[len * BB + b];
        g_part[b] = zf - (S + tr_sh[0 * CC + last]);   // trans[PAD, last]
    }
}

// Deterministic tree reduction of the 1024 per-chain results.
__global__ void crf_reduce(float* __restrict__ out) {
    __shared__ float sh[256];
    const int t = threadIdx.x;
    float s = 0.0f;
#pragma unroll
    for (int k = 0; k < 4; k++) s += g_part[t + 256 * k];
    sh[t] = s;
    __syncthreads();
    for (int o = 128; o; o >>= 1) {
        if (t < o) sh[t] += sh[t + o];
        __syncthreads();
    }
    if (t == 0) out[0] = sh[0] * (1.0f / 1024.0f);
}

extern "C" void kernel_launch(void* const* d_in, const int* in_sizes, int n_in,
                              void* d_out, int out_size) {
    const float* h     = nullptr;
    const int*   y0    = nullptr;
    const float* mask  = nullptr;
    const float* trans = nullptr;
    for (int i = 0; i < n_in; i++) {
        const long n = (long)in_sizes[i];
        if      (n == (long)TT * BB * CC)  h     = (const float*)d_in[i];
        else if (n == (long)(TT + 1) * BB) y0    = (const int*)d_in[i];
        else if (n == (long)TT * BB)       mask  = (const float*)d_in[i];
        else if (n == (long)CC * CC)       trans = (const float*)d_in[i];
    }

    crf_len<<<8, BB>>>(mask);        // launch 1
    crf_sort<<<1, BB>>>();           // launch 2
    crf_nop<<<1, 32>>>();            // launch 3 (pad: puts crf_chain at #6
    crf_nop<<<1, 32>>>();            // launch 4  for ncu -s 5 -c 1 capture)
    crf_nop<<<1, 32>>>();            // launch 5
    crf_chain<<<GRIDC, NWARP * 32>>>(h, y0, mask, trans);   // launch 6
    crf_reduce<<<1, 256>>>((float*)d_out);                  // launch 7
}

// round 15
// speedup vs baseline: 1.2346x; 1.0589x over previous
#include <cuda_runtime.h>
#include <cstdint>

#define TT 512
#define BB 1024
#define CC 64
#define FULLMASK 0xFFFFFFFFu
#define GRID 148
#define NWARP 8

typedef unsigned long long u64;

__device__ float g_part[BB];
__device__ int   g_lpart[8][BB];
__device__ int   g_len[BB];
__device__ int   g_order[BB];      // chain ids, descending length

// ---- packed f32x2 helpers ----
static __device__ __forceinline__ u64 fma2(u64 a, u64 b, u64 c) {
    u64 r;
    asm("fma.rn.f32x2 %0, %1, %2, %3;" : "=l"(r) : "l"(a), "l"(b), "l"(c));
    return r;
}
static __device__ __forceinline__ u64 add2(u64 a, u64 b) {
    u64 r;
    asm("add.rn.f32x2 %0, %1, %2;" : "=l"(r) : "l"(a), "l"(b));
    return r;
}
static __device__ __forceinline__ u64 pack2(float lo, float hi) {
    u64 r;
    asm("mov.b64 %0, {%1, %2};" : "=l"(r) : "f"(lo), "f"(hi));
    return r;
}
static __device__ __forceinline__ float hadd2(u64 a) {
    float lo, hi;
    asm("mov.b64 {%0, %1}, %2;" : "=f"(lo), "=f"(hi) : "l"(a));
    return lo + hi;
}

// ---- pre-pass 1: per-slice partial lengths (coalesced) ----
__global__ void crf_len(const float* __restrict__ mask) {
    const int b = threadIdx.x;
    const int k = blockIdx.x;
    float c = 0.0f;
#pragma unroll 8
    for (int t = k * 64; t < (k + 1) * 64; t++)
        c += mask[t * BB + b];
    g_lpart[k][b] = (int)c;
}

// ---- pre-pass 2: counting sort by length, descending ----
__global__ void crf_sort() {
    __shared__ int hist[TT + 1];
    __shared__ int off[TT + 1];
    const int b = threadIdx.x;
    if (b <= TT) hist[b] = 0;
    __syncthreads();
    int len = 0;
#pragma unroll
    for (int k = 0; k < 8; k++) len += g_lpart[k][b];
    g_len[b] = len;
    atomicAdd(&hist[len], 1);
    __syncthreads();
    if (b == 0) {
        int acc = 0;
        for (int l = TT; l >= 0; l--) { off[l] = acc; acc += hist[l]; }
    }
    __syncthreads();
    const int r = atomicAdd(&off[len], 1);
    g_order[r] = b;
}

// One warp per chain. SMSP s hosts wid s and wid s+4; BAND pairs the longest
// band with the shortest so each SMSP gets ~equal total steps (R9 mapping).
__global__ void __launch_bounds__(NWARP * 32) crf_chain(
    const float* __restrict__ h,      // (T, B, C)
    const int*   __restrict__ y0,     // (T+1, B)
    const float* __restrict__ mask,   // unused
    const float* __restrict__ trans)  // (C, C)
{
    __shared__ __align__(16) float tr_sh[CC * CC];
    __shared__ __align__(16) float E_sh[CC * CC];          // exp(trans)
    __shared__ __align__(16) u64   p_sh[NWARP][2][32];

    const int tid  = threadIdx.x;
    const int lane = tid & 31;
    const int wid  = tid >> 5;

    // issue chain-id loads early: their latency hides under the smem fill
    const int band = (wid < 4) ? wid : 11 - wid;
    const int rank = band * GRID + blockIdx.x;
    int b = 0, len = 0;
    const bool active = (rank < BB);
    if (active) {
        b   = g_order[rank];
        len = g_len[b];
    }

    // cooperative fill: trans -> tr_sh, exp(trans) -> E_sh
    {
        const float4* g4 = (const float4*)trans;
        float4*       t4 = (float4*)tr_sh;
        float4*       e4 = (float4*)E_sh;
#pragma unroll
        for (int k = 0; k < (CC * CC / 4) / (NWARP * 32); k++) {
            const int    idx = tid + NWARP * 32 * k;
            const float4 v   = g4[idx];
            t4[idx] = v;
            float4 e;
            e.x = __expf(v.x); e.y = __expf(v.y);
            e.z = __expf(v.z); e.w = __expf(v.w);
            e4[idx] = e;
        }
    }
    __syncthreads();

    if (!active) return;
    const int j0 = 2 * lane;
    const int j1 = 2 * lane + 1;

    // E rows -> registers as packed f32x2 pairs
    u64 e0[32], e1[32];
    {
        const ulonglong2* ge = (const ulonglong2*)E_sh;
#pragma unroll
        for (int k = 0; k < 16; k++) {
            ulonglong2 q0 = ge[j0 * 16 + k];
            ulonglong2 q1 = ge[j1 * 16 + k];
            e0[2 * k] = q0.x; e0[2 * k + 1] = q0.y;
            e1[2 * k] = q1.x; e1[2 * k + 1] = q1.y;
        }
    }

    // init: v one-hot at SOS(=1); Ccum = 0; normalizer seeded to 1
    float pc0 = (j0 == 1) ? 1.0f : 0.0f;
    float pc1 = (j1 == 1) ? 1.0f : 0.0f;
    float nrm_reg = 1.0f;     // lane 1's copy tracks v[3]
    float Ccum = 0.0f;
    p_sh[wid][0][lane] = pack2(pc0, pc1);
    __syncwarp();

    // 8-deep indexed h ring (float2/lane/step), slot = t & 7
    const float2* hp   = (const float2*)h;
    const int     HROW = BB * CC / 2;
    const int     hoff = b * (CC / 2) + lane;
    float2 hb[8];
#pragma unroll
    for (int k = 0; k < 8; k++) hb[k] = hp[(size_t)k * HROW + hoff];

    int buf = 0;

    // one step; s = static ring slot; norm every 4 steps (range-safe).
    // 8-way accumulator tree: fma depth 4 (16 cyc) + 3-level add2 reduce.
    auto step = [&](int tcur, int s, bool do_norm) __attribute__((always_inline)) {
        const float2 hc  = hb[s];
        float r = 1.0f;
        if (do_norm) {
            const float nrm = __shfl_sync(FULLMASK, nrm_reg, 1);
            r = __fdividef(1.0f, nrm);
            Ccum += __logf(nrm);
        }
        const float eh0 = __expf(hc.x);
        const float eh1 = __expf(hc.y);

        const ulonglong2* pv = (const ulonglong2*)p_sh[wid][buf];
        u64 a0[8] = {0, 0, 0, 0, 0, 0, 0, 0};
        u64 a1[8] = {0, 0, 0, 0, 0, 0, 0, 0};
#pragma unroll
        for (int k = 0; k < 16; k++) {
            ulonglong2 q = pv[k];
            const int  c = 2 * (k & 3);          // 8 chains, depth 4
            a0[c]     = fma2(e0[2 * k],     q.x, a0[c]);
            a0[c + 1] = fma2(e0[2 * k + 1], q.y, a0[c + 1]);
            a1[c]     = fma2(e1[2 * k],     q.x, a1[c]);
            a1[c + 1] = fma2(e1[2 * k + 1], q.y, a1[c + 1]);
        }
        const u64 b00 = add2(a0[0], a0[1]), b01 = add2(a0[2], a0[3]);
        const u64 b02 = add2(a0[4], a0[5]), b03 = add2(a0[6], a0[7]);
        const u64 b10 = add2(a1[0], a1[1]), b11 = add2(a1[2], a1[3]);
        const u64 b12 = add2(a1[4], a1[5]), b13 = add2(a1[6], a1[7]);
        const float acc0 = hadd2(add2(add2(b00, b01), add2(b02, b03)));
        const float acc1 = hadd2(add2(add2(b10, b11), add2(b12, b13)));

        if (do_norm) { pc0 = acc0 * r * eh0; pc1 = acc1 * r * eh1; }
        else         { pc0 = acc0 * eh0;     pc1 = acc1 * eh1;     }
        nrm_reg = pc1;                        // lane 1's pc1 == v[3]
        p_sh[wid][buf ^ 1][lane] = pack2(pc0, pc1);
        buf ^= 1;

        int tf = tcur + 8;
        if (tf > TT - 1) tf = TT - 1;
        hb[s] = hp[(size_t)tf * HROW + hoff];
        __syncwarp();
    };

    // counted main loop, then break-able tail chunk (warp-private control flow)
    const int len8 = len & ~7;
    int t = 0;
#pragma unroll 1
    for (; t < len8; t += 8) {
#pragma unroll
        for (int s = 0; s < 8; s++) step(t + s, s, (s & 3) == 0);
    }
#pragma unroll
    for (int s = 0; s < 8; s++) {
        if (t + s >= len) break;
        step(t + s, s, (s & 3) == 0);
    }

    // final: Zf = Ccum + log( sum_j v_j * exp(trans[EOS, j]) )
    float v = pc0 * E_sh[2 * CC + j0] + pc1 * E_sh[2 * CC + j1];
#pragma unroll
    for (int o = 16; o; o >>= 1) v += __shfl_xor_sync(FULLMASK, v, o);
    const float zf = Ccum + __logf(v);

    // score: S = sum_{t<min(len,T-1)} h[t,b,y0[t+1]] + trans[y0[t+1],y0[t]]
    float S = 0.0f;
    {
        const int tmax = (len < TT - 1) ? len : (TT - 1);
#pragma unroll
        for (int k = 0; k < 16; k++) {
            const int tt = lane + 32 * k;
            if (tt < tmax) {
                const int ya = y0[tt * BB + b];
                const int yb = y0[(tt + 1) * BB + b];
                const float hv = h[(size_t)tt * (BB * CC) + b * CC + yb];
                S += hv + tr_sh[yb * CC + ya];
            }
        }
#pragma unroll
        for (int o = 16; o; o >>= 1) S += __shfl_xor_sync(FULLMASK, S, o);
    }

    if (lane == 0) {
        const int last = y0[len * BB + b];
        g_part[b] = zf - (S + tr_sh[0 * CC + last]);   // trans[PAD, last]
    }
}

// Deterministic tree reduction of the 1024 per-chain results.
__global__ void crf_reduce(float* __restrict__ out) {
    __shared__ float sh[256];
    const int t = threadIdx.x;
    float s = 0.0f;
#pragma unroll
    for (int k = 0; k < 4; k++) s += g_part[t + 256 * k];
    sh[t] = s;
    __syncthreads();
    for (int o = 128; o; o >>= 1) {
        if (t < o) sh[t] += sh[t + o];
        __syncthreads();
    }
    if (t == 0) out[0] = sh[0] * (1.0f / 1024.0f);
}

extern "C" void kernel_launch(void* const* d_in, const int* in_sizes, int n_in,
                              void* d_out, int out_size) {
    const float* h     = nullptr;
    const int*   y0    = nullptr;
    const float* mask  = nullptr;
    const float* trans = nullptr;
    for (int i = 0; i < n_in; i++) {
        const long n = (long)in_sizes[i];
        if      (n == (long)TT * BB * CC)  h     = (const float*)d_in[i];
        else if (n == (long)(TT + 1) * BB) y0    = (const int*)d_in[i];
        else if (n == (long)TT * BB)       mask  = (const float*)d_in[i];
        else if (n == (long)CC * CC)       trans = (const float*)d_in[i];
    }

    crf_len<<<8, BB>>>(mask);
    crf_sort<<<1, BB>>>();
    crf_chain<<<GRID, NWARP * 32>>>(h, y0, mask, trans);
    crf_reduce<<<1, 256>>>((float*)d_out);
}